// round 17
// baseline (speedup 1.0000x reference)
#include <cuda_runtime.h>
#include <cuda_bf16.h>
#include <math.h>

// Problem constants
#define NROWS 8192      // B*T
#define DD    512
#define NH    8
#define HDIM  64
#define FF    2048
#define VV    8192
#define TT    1024
#define BB    8
#define LL    6
#define MPAD  1536      // padded masked-row count

// ---------------- scratch (device globals; no allocation allowed) ----------------
__device__ float g_hx  [MPAD * DD];      // exact embed+PE at masked rows (fp32)
__device__ float g_h   [MPAD * DD];      // gathered fp32 LN rows (target path)
__device__ float g_xe  [NROWS * DD];     // residual stream fp32
__device__ float g_z   [MPAD * DD];      // gathered projected codes
__device__ float g_e2  [VV];
__device__ int   g_rowidx[NROWS];
__device__ int   g_M;
__device__ int   g_maskmode;
__device__ float g_pbv [MPAD * 16];
__device__ int   g_pbi [MPAD * 16];
__device__ int   g_tgt [NROWS];
__device__ float g_ent [NROWS];
__device__ float g_logits[(size_t)MPAD * VV];   // masked logits (fp32)

// bf16 activation buffers (packed pairs)
__device__ unsigned g_xs_bf [NROWS * DD / 2];   // xs in bf16
__device__ unsigned g_h_bf  [NROWS * DD / 2];
__device__ unsigned g_qkv_bf[NROWS * 3 * DD / 2];
__device__ unsigned g_o_bf  [NROWS * DD / 2];
__device__ unsigned g_f_bf  [NROWS * FF / 2];
__device__ unsigned g_gz_bf [MPAD * DD / 2];    // gathered final-LN rows (bf16)
// bf16 weights
__device__ unsigned g_we_bf  [DD * DD / 2];
__device__ unsigned g_wqkv_bf[LL * DD * 3 * DD / 2];
__device__ unsigned g_wo_bf  [LL * DD * DD / 2];
__device__ unsigned g_w1_bf  [LL * DD * FF / 2];
__device__ unsigned g_w2_bf  [LL * FF * DD / 2];
__device__ unsigned g_top_bf [DD * VV / 2];

// pack two floats into bf16x2 (lo in lower half)
__device__ __forceinline__ unsigned packbf(float lo, float hi) {
    unsigned r;
    asm("cvt.rn.bf16x2.f32 %0, %1, %2;" : "=r"(r) : "f"(hi), "f"(lo));
    return r;
}

#define MMA_BF16(acc, a0, a1, a2, a3, b0, b1)                                  \
    asm volatile(                                                              \
        "mma.sync.aligned.m16n8k16.row.col.f32.bf16.bf16.f32 "                 \
        "{%0,%1,%2,%3}, {%4,%5,%6,%7}, {%8,%9}, {%0,%1,%2,%3};"                \
        : "+f"(acc[0]), "+f"(acc[1]), "+f"(acc[2]), "+f"(acc[3])               \
        : "r"(a0), "r"(a1), "r"(a2), "r"(a3), "r"(b0), "r"(b1))

#define LDSM4(r0, r1, r2, r3, addr)                                            \
    asm volatile("ldmatrix.sync.aligned.m8n8.x4.shared.b16 {%0,%1,%2,%3}, [%4];" \
                 : "=r"(r0), "=r"(r1), "=r"(r2), "=r"(r3) : "r"(addr))

#define LDSM4T(r0, r1, r2, r3, addr)                                           \
    asm volatile("ldmatrix.sync.aligned.m8n8.x4.trans.shared.b16 {%0,%1,%2,%3}, [%4];" \
                 : "=r"(r0), "=r"(r1), "=r"(r2), "=r"(r3) : "r"(addr))

#define CP16(dst, src)                                                         \
    asm volatile("cp.async.ca.shared.global [%0], [%1], 16;" :: "r"(dst), "l"(src))

// ---------------- weight f32 -> bf16 conversion ----------------
__global__ void convert_kernel(const float2* __restrict__ src, unsigned* __restrict__ dst, int n) {
    int i = blockIdx.x * 256 + threadIdx.x;
    if (i < n) {
        float2 v = src[i];
        dst[i] = packbf(v.x, v.y);
    }
}

// ---------------- mask dtype detection ----------------
__global__ void detect_mask_kernel(const void* mask) {
    const unsigned int* w = (const unsigned int*)mask;
    __shared__ int hasF, hasB;
    if (threadIdx.x == 0) { hasF = 0; hasB = 0; }
    __syncthreads();
    for (int i = threadIdx.x; i < 2048; i += blockDim.x) {
        unsigned int x = w[i];
        if (x == 0x3F800000u) atomicOr(&hasF, 1);
        else if (x > 1u)      atomicOr(&hasB, 1);
    }
    __syncthreads();
    if (threadIdx.x == 0) g_maskmode = hasF ? 2 : (hasB ? 0 : 1);
}

__device__ __forceinline__ bool maskAt(const void* m, int i) {
    int mode = g_maskmode;
    if (mode == 0) return ((const unsigned char*)m)[i] != 0;
    if (mode == 1) return ((const int*)m)[i] != 0;
    return ((const float*)m)[i] != 0.0f;
}

// ---------------- deterministic compaction ----------------
__global__ void compact_kernel(const void* mask, const int* __restrict__ lens) {
    int tid = threadIdx.x;
    bool pr[8];
    int cnt = 0;
    #pragma unroll
    for (int j = 0; j < 8; j++) {
        int i = tid * 8 + j;
        int b = i >> 10, t = i & 1023;
        bool p = maskAt(mask, i) && (t < lens[b]);
        pr[j] = p;
        cnt += p ? 1 : 0;
    }
    __shared__ int s[1024];
    s[tid] = cnt;
    __syncthreads();
    for (int off = 1; off < 1024; off <<= 1) {
        int v = (tid >= off) ? s[tid - off] : 0;
        __syncthreads();
        s[tid] += v;
        __syncthreads();
    }
    int pos = s[tid] - cnt;
    #pragma unroll
    for (int j = 0; j < 8; j++)
        if (pr[j]) g_rowidx[pos++] = tid * 8 + j;
    if (tid == 1023) g_M = s[1023];
}

// ---------------- 0.5*||e_v||^2 ----------------
__global__ void e2_kernel(const float* __restrict__ emb) {
    int v = blockIdx.x * blockDim.x + threadIdx.x;
    float s = 0.f;
    for (int e = 0; e < DD; e++) {
        float x = emb[(size_t)e * VV + v];
        s += x * x;
    }
    g_e2[v] = 0.5f * s;
}

// ---------------- fp32 GEMM (target path: exact) ----------------
// epi: 0 none, 3 +sinusoidal PE. gidx: optional A-row gather (PE uses gidx row's t).
__global__ void sgemm(const float* __restrict__ A, const float* __restrict__ Bm,
                      float* __restrict__ C, const float* __restrict__ Res,
                      int M, int N, int K, int epi, const int* __restrict__ gidx) {
    int m0 = blockIdx.y * 128;
    int n0 = blockIdx.x * 128;

    __shared__ float As[8][128];
    __shared__ float Bs[8][128];

    int tid = threadIdx.x;
    int tx = tid & 15, ty = tid >> 4;
    int lr = tid >> 1;
    int lc = (tid & 1) * 4;
    int br = tid >> 5;
    int bc = (tid & 31) * 4;

    int arow = m0 + lr;
    if (gidx) arow = gidx[arow];

    float acc[8][8];
    #pragma unroll
    for (int i = 0; i < 8; i++)
        #pragma unroll
        for (int j = 0; j < 8; j++) acc[i][j] = 0.f;

    for (int k0 = 0; k0 < K; k0 += 8) {
        float4 av = *(const float4*)(A + (size_t)arow * K + k0 + lc);
        As[lc + 0][lr] = av.x;
        As[lc + 1][lr] = av.y;
        As[lc + 2][lr] = av.z;
        As[lc + 3][lr] = av.w;
        float4 bv = *(const float4*)(Bm + (size_t)(k0 + br) * N + n0 + bc);
        *(float4*)&Bs[br][bc] = bv;
        __syncthreads();

        #pragma unroll
        for (int k = 0; k < 8; k++) {
            float a0[8], b0[8];
            #pragma unroll
            for (int i = 0; i < 8; i++) a0[i] = As[k][ty * 8 + i];
            #pragma unroll
            for (int j = 0; j < 8; j++) b0[j] = Bs[k][tx * 8 + j];
            #pragma unroll
            for (int i = 0; i < 8; i++)
                #pragma unroll
                for (int j = 0; j < 8; j++) acc[i][j] += a0[i] * b0[j];
        }
        __syncthreads();
    }

    #pragma unroll
    for (int i = 0; i < 8; i++) {
        int r = m0 + ty * 8 + i;
        size_t base = (size_t)r * N + n0 + tx * 8;
        int orow = gidx ? gidx[r] : r;
        #pragma unroll
        for (int j = 0; j < 8; j++) {
            float v = acc[i][j];
            if (epi == 1)      v += Res[base + j];
            else if (epi == 2) v = fmaxf(v, 0.f);
            else if (epi == 3) {
                int d = n0 + tx * 8 + j;
                int t = orow & 1023;
                int d2 = d & ~1;
                float denom = expf(((float)d2 / 512.0f) * 9.210340371976184f);
                float ang = (float)t / denom;
                v += (d & 1) ? cosf(ang) : sinf(ang);
            }
            C[base + j] = v;
        }
    }
}

// ---------------- bf16 tensor-core GEMM, 4-stage cp.async ring ----------------
// dyn: 0 none, 1 early-exit past round128(g_M), 2 dead-row-block skip via lens
// epi: 0 fp32; 1 fp32 +Res; 2 bf16 relu; 3 bf16; 4 fp32 +PE then mask-select memb
#define BF_STG_H 9472           // halves per stage (128*40 + 32*136)
#define BF_SMEM  (4 * BF_STG_H * 2)
__global__ void __launch_bounds__(256, 2)
bfgemm(const unsigned short* __restrict__ A, const unsigned short* __restrict__ B,
       void* __restrict__ Cv, const float* __restrict__ Res,
       int M, int N, int K, int epi, int dyn, const int* __restrict__ lens,
       const void* __restrict__ mask, const float* __restrict__ memb) {
    extern __shared__ unsigned short sdyn[];

    const int m0 = blockIdx.y * 128;
    if (dyn == 1) {
        int Mro = (g_M + 127) & ~127;
        if (m0 >= Mro) return;
    }
    bool dead = false;
    if (dyn == 2) dead = ((m0 & 1023) >= lens[m0 >> 10]);

    const int n0 = blockIdx.x * 128;
    const int tid = threadIdx.x;
    const int lane = tid & 31;
    const int warp = tid >> 5;
    const int wm0 = (warp & 1) * 64;
    const int wn0 = (warp >> 1) * 32;
    const int tr = lane >> 2;
    const int tc = lane & 3;

    float acc[4][4][4];
    #pragma unroll
    for (int mi = 0; mi < 4; mi++)
        #pragma unroll
        for (int ni = 0; ni < 4; ni++)
            #pragma unroll
            for (int c = 0; c < 4; c++) acc[mi][ni][c] = 0.f;

    if (!dead) {
        const int ar  = tid >> 1;
        const int acb = (tid & 1) * 2;
        const int bkr = tid >> 3;
        const int bcb = (tid & 7) * 2;

        const unsigned short* aSrc = A + (size_t)(m0 + ar) * K + acb * 8;
        const unsigned short* bSrc = B + (size_t)bkr * N + n0 + bcb * 8;

        unsigned aSh[4], bSh[4], aDst[4], bDst[4];
        #pragma unroll
        for (int st = 0; st < 4; st++) {
            unsigned base = (unsigned)__cvta_generic_to_shared(sdyn + st * BF_STG_H);
            aSh[st]  = base;
            bSh[st]  = base + 10240;
            aDst[st] = base + (unsigned)((ar * 40 + acb * 8) * 2);
            bDst[st] = base + 10240 + (unsigned)((bkr * 136 + bcb * 8) * 2);
        }

        const int alr = lane & 15;
        const int ahi = lane >> 4;
        const unsigned aOff = (unsigned)((alr * 40 + ahi * 8) * 2);
        const int bg = lane >> 3;
        const int bkrow = (lane & 7) + (bg & 1) * 8;
        const unsigned bOff = (unsigned)((bkrow * 136 + wn0 + (bg >> 1) * 8) * 2);

        const int NK = K >> 5;

        #pragma unroll
        for (int ch = 0; ch < 3; ch++) {
            const unsigned short* as1 = aSrc + ch * 32;
            const unsigned short* bs1 = bSrc + (size_t)(ch * 32) * N;
            CP16(aDst[ch],      as1);
            CP16(aDst[ch] + 16, as1 + 8);
            CP16(bDst[ch],      bs1);
            CP16(bDst[ch] + 16, bs1 + 8);
            asm volatile("cp.async.commit_group;");
        }

        int s = 0;
        for (int it = 0; it < NK; it++) {
            if (it < NK - 2)      asm volatile("cp.async.wait_group 2;");
            else if (it == NK - 2) asm volatile("cp.async.wait_group 1;");
            else                   asm volatile("cp.async.wait_group 0;");
            __syncthreads();

            if (it + 3 < NK) {
                int nb = s + 3; if (nb >= 4) nb -= 4;
                int k0 = (it + 3) * 32;
                const unsigned short* as2 = aSrc + k0;
                const unsigned short* bs2 = bSrc + (size_t)k0 * N;
                CP16(aDst[nb],      as2);
                CP16(aDst[nb] + 16, as2 + 8);
                CP16(bDst[nb],      bs2);
                CP16(bDst[nb] + 16, bs2 + 8);
                asm volatile("cp.async.commit_group;");
            }

            #pragma unroll
            for (int ks = 0; ks < 2; ks++) {
                unsigned a[4][4], b[4][2];
                #pragma unroll
                for (int mi = 0; mi < 4; mi++) {
                    unsigned addr = aSh[s] + aOff + (unsigned)((wm0 + mi * 16) * 80 + ks * 32);
                    LDSM4(a[mi][0], a[mi][1], a[mi][2], a[mi][3], addr);
                }
                #pragma unroll
                for (int np = 0; np < 2; np++) {
                    unsigned addr = bSh[s] + bOff + (unsigned)(np * 32 + ks * 4352);
                    LDSM4T(b[2 * np][0], b[2 * np][1], b[2 * np + 1][0], b[2 * np + 1][1], addr);
                }
                #pragma unroll
                for (int mi = 0; mi < 4; mi++)
                    #pragma unroll
                    for (int ni = 0; ni < 4; ni++)
                        MMA_BF16(acc[mi][ni], a[mi][0], a[mi][1], a[mi][2], a[mi][3],
                                 b[ni][0], b[ni][1]);
            }
            s = (s + 1 == 4) ? 0 : s + 1;
        }
    }

    #pragma unroll
    for (int mi = 0; mi < 4; mi++) {
        #pragma unroll
        for (int ni = 0; ni < 4; ni++) {
            int r0 = m0 + wm0 + mi * 16 + tr;
            int cc = n0 + wn0 + ni * 8 + tc * 2;
            float v00 = acc[mi][ni][0], v01 = acc[mi][ni][1];
            float v10 = acc[mi][ni][2], v11 = acc[mi][ni][3];
            size_t i0 = (size_t)r0 * N + cc;
            size_t i1 = (size_t)(r0 + 8) * N + cc;
            if (epi == 0) {
                *(float2*)((float*)Cv + i0) = make_float2(v00, v01);
                *(float2*)((float*)Cv + i1) = make_float2(v10, v11);
            } else if (epi == 1) {
                float2 r0v = *(const float2*)(Res + i0);
                float2 r1v = *(const float2*)(Res + i1);
                *(float2*)((float*)Cv + i0) = make_float2(v00 + r0v.x, v01 + r0v.y);
                *(float2*)((float*)Cv + i1) = make_float2(v10 + r1v.x, v11 + r1v.y);
            } else if (epi == 2) {
                ((unsigned*)Cv)[i0 >> 1] = packbf(fmaxf(v00, 0.f), fmaxf(v01, 0.f));
                ((unsigned*)Cv)[i1 >> 1] = packbf(fmaxf(v10, 0.f), fmaxf(v11, 0.f));
            } else if (epi == 4) {
                // embed epilogue: +PE, then mask-select memb (per row)
                int d = cc;  // even
                float denom = expf(((float)d / 512.0f) * 9.210340371976184f);
                float a0 = (float)(r0 & 1023) / denom;
                float a1 = (float)((r0 + 8) & 1023) / denom;
                v00 += sinf(a0); v01 += cosf(a0);
                v10 += sinf(a1); v11 += cosf(a1);
                float m0f = memb[d], m1f = memb[d + 1];
                bool mk0 = maskAt(mask, r0), mk1 = maskAt(mask, r0 + 8);
                *(float2*)((float*)Cv + i0) = mk0 ? make_float2(m0f, m1f) : make_float2(v00, v01);
                *(float2*)((float*)Cv + i1) = mk1 ? make_float2(m0f, m1f) : make_float2(v10, v11);
            } else {
                ((unsigned*)Cv)[i0 >> 1] = packbf(v00, v01);
                ((unsigned*)Cv)[i1 >> 1] = packbf(v10, v11);
            }
        }
    }
}

// ---------------- layernorm bf16 out (dead-row skip via lens) ----------------
__global__ void ln_bf_kernel(const float* __restrict__ in, unsigned* __restrict__ out,
                             const float* __restrict__ gam, const float* __restrict__ bet,
                             const int* __restrict__ lens) {
    int row = blockIdx.x;
    int tid = threadIdx.x;
    if ((row & 1023) >= lens[row >> 10]) {
        out[row * 256 + tid * 2]     = 0u;
        out[row * 256 + tid * 2 + 1] = 0u;
        return;
    }
    const float4* xp = (const float4*)(in + (size_t)row * DD);
    float4 v = xp[tid];
    __shared__ float red[4];
    float s = v.x + v.y + v.z + v.w;
    #pragma unroll
    for (int o = 16; o; o >>= 1) s += __shfl_down_sync(0xffffffffu, s, o);
    if ((tid & 31) == 0) red[tid >> 5] = s;
    __syncthreads();
    float mean = (red[0] + red[1] + red[2] + red[3]) * (1.0f / 512.0f);
    float dx = v.x - mean, dy = v.y - mean, dz = v.z - mean, dw = v.w - mean;
    float sq = dx * dx + dy * dy + dz * dz + dw * dw;
    #pragma unroll
    for (int o = 16; o; o >>= 1) sq += __shfl_down_sync(0xffffffffu, sq, o);
    __syncthreads();
    if ((tid & 31) == 0) red[tid >> 5] = sq;
    __syncthreads();
    float var = (red[0] + red[1] + red[2] + red[3]) * (1.0f / 512.0f);
    float rstd = rsqrtf(var + 1e-5f);
    float4 go = ((const float4*)gam)[tid];
    float4 bo = ((const float4*)bet)[tid];
    float ox = dx * rstd * go.x + bo.x;
    float oy = dy * rstd * go.y + bo.y;
    float oz = dz * rstd * go.z + bo.z;
    float ow = dw * rstd * go.w + bo.w;
    out[row * 256 + tid * 2]     = packbf(ox, oy);
    out[row * 256 + tid * 2 + 1] = packbf(oz, ow);
}

// ---------------- plain LN fp32 over compacted rows (target path) ----------------
__global__ void ln_plain_f32(const float* __restrict__ in, float* __restrict__ out,
                             const float* __restrict__ gam, const float* __restrict__ bet) {
    int row = blockIdx.x;      // 0..MPAD-1 (pad rows process garbage; discarded later)
    int tid = threadIdx.x;     // 128
    const float4* xp = (const float4*)(in + (size_t)row * DD);
    float4 v = xp[tid];
    __shared__ float red[4];
    float s = v.x + v.y + v.z + v.w;
    #pragma unroll
    for (int o = 16; o; o >>= 1) s += __shfl_down_sync(0xffffffffu, s, o);
    if ((tid & 31) == 0) red[tid >> 5] = s;
    __syncthreads();
    float mean = (red[0] + red[1] + red[2] + red[3]) * (1.0f / 512.0f);
    float dx = v.x - mean, dy = v.y - mean, dz = v.z - mean, dw = v.w - mean;
    float sq = dx * dx + dy * dy + dz * dz + dw * dw;
    #pragma unroll
    for (int o = 16; o; o >>= 1) sq += __shfl_down_sync(0xffffffffu, sq, o);
    __syncthreads();
    if ((tid & 31) == 0) red[tid >> 5] = sq;
    __syncthreads();
    float var = (red[0] + red[1] + red[2] + red[3]) * (1.0f / 512.0f);
    float rstd = rsqrtf(var + 1e-5f);
    float4 go = ((const float4*)gam)[tid];
    float4 bo = ((const float4*)bet)[tid];
    float4 o4;
    o4.x = dx * rstd * go.x + bo.x;
    o4.y = dy * rstd * go.y + bo.y;
    o4.z = dz * rstd * go.z + bo.z;
    o4.w = dw * rstd * go.w + bo.w;
    ((float4*)out)[row * 128 + tid] = o4;
}

// ---------------- gathered final-LN -> compact bf16 rows (zero-padded) ----------------
__global__ void gather_ln_bf(const float* __restrict__ in, unsigned* __restrict__ out,
                             const float* __restrict__ gam, const float* __restrict__ bet) {
    int mrow = blockIdx.x;     // 0..MPAD-1
    int tid = threadIdx.x;     // 128
    if (mrow >= g_M) {
        ((uint2*)out)[mrow * 128 + tid] = make_uint2(0u, 0u);
        return;
    }
    int row = g_rowidx[mrow];
    const float4* xp = (const float4*)(in + (size_t)row * DD);
    float4 v = xp[tid];
    __shared__ float red[4];
    float s = v.x + v.y + v.z + v.w;
    #pragma unroll
    for (int o = 16; o; o >>= 1) s += __shfl_down_sync(0xffffffffu, s, o);
    if ((tid & 31) == 0) red[tid >> 5] = s;
    __syncthreads();
    float mean = (red[0] + red[1] + red[2] + red[3]) * (1.0f / 512.0f);
    float dx = v.x - mean, dy = v.y - mean, dz = v.z - mean, dw = v.w - mean;
    float sq = dx * dx + dy * dy + dz * dz + dw * dw;
    #pragma unroll
    for (int o = 16; o; o >>= 1) sq += __shfl_down_sync(0xffffffffu, sq, o);
    __syncthreads();
    if ((tid & 31) == 0) red[tid >> 5] = sq;
    __syncthreads();
    float var = (red[0] + red[1] + red[2] + red[3]) * (1.0f / 512.0f);
    float rstd = rsqrtf(var + 1e-5f);
    float4 go = ((const float4*)gam)[tid];
    float4 bo = ((const float4*)bet)[tid];
    float ox = dx * rstd * go.x + bo.x;
    float oy = dy * rstd * go.y + bo.y;
    float oz = dz * rstd * go.z + bo.z;
    float ow = dw * rstd * go.w + bo.w;
    out[mrow * 256 + tid * 2]     = packbf(ox, oy);
    out[mrow * 256 + tid * 2 + 1] = packbf(oz, ow);
}

// ---------------- bf16 mma flash attention, 128-row Q tile, KV + Q early-exit ----------------
#define ATT_SMEM ((128 * 36 + 4 * 64 * 36) * 4)
__global__ void __launch_bounds__(256)
attn_mma_kernel(const unsigned short* __restrict__ qkv, const int* __restrict__ lens,
                unsigned* __restrict__ out) {
    extern __shared__ unsigned att_s[];
    unsigned* Qs  = att_s;                    // 128*36 words
    unsigned* Ks0 = att_s + 128 * 36;
    unsigned* Ks1 = Ks0 + 64 * 36;
    unsigned* Vs0 = Ks1 + 64 * 36;
    unsigned* Vs1 = Vs0 + 64 * 36;

    int qt = blockIdx.x;        // 0..7
    int bh = blockIdx.y;
    int b = bh >> 3, h = bh & 7;
    int tid = threadIdx.x;
    int lane = tid & 31, w = tid >> 5;   // 8 warps
    int tr = lane >> 2, tc = lane & 3;
    int len = lens[b];

    if (qt * 128 >= len) {
        for (int idx = tid; idx < 128 * 2; idx += 256) {
            int rr = idx >> 1, hh = idx & 1;
            uint4* p = (uint4*)(out + (size_t)(b * 1024 + qt * 128 + rr) * 256 + h * 32 + hh * 16);
            p[0] = make_uint4(0u, 0u, 0u, 0u);
            p[1] = make_uint4(0u, 0u, 0u, 0u);
            p[2] = make_uint4(0u, 0u, 0u, 0u);
            p[3] = make_uint4(0u, 0u, 0u, 0u);
        }
        return;
    }

    int nt = (len + 63) >> 6;

    {
        int qr = tid >> 1, qhalf = tid & 1;
        const uint4* qp = (const uint4*)(qkv + (size_t)(b * 1024 + qt * 128 + qr) * 1536 + h * 64 + qhalf * 32);
        #pragma unroll
        for (int c = 0; c < 4; c++) {
            uint4 v = qp[c];
            int o = qr * 36 + qhalf * 16 + 4 * c;
            Qs[o] = v.x; Qs[o + 1] = v.y; Qs[o + 2] = v.z; Qs[o + 3] = v.w;
        }
    }

    int r = tid >> 2, qq = tid & 3;
    const unsigned short* kSrcBase = qkv + (size_t)(b * 1024 + r) * 1536 + 512 + h * 64 + qq * 16;
    const unsigned short* vSrcBase = kSrcBase + 512;
    unsigned kDst[2];
    kDst[0] = (unsigned)__cvta_generic_to_shared(Ks0 + r * 36 + qq * 8);
    kDst[1] = (unsigned)__cvta_generic_to_shared(Ks1 + r * 36 + qq * 8);

    CP16(kDst[0],      kSrcBase);
    CP16(kDst[0] + 16, kSrcBase + 8);
    asm volatile("cp.async.commit_group;");
    uint4 vr0, vr1;
    {
        const uint4* vp = (const uint4*)vSrcBase;
        vr0 = vp[0]; vr1 = vp[1];
        unsigned short* vh = (unsigned short*)Vs0;
        int d0 = qq * 16;
        vh[(d0 + 0) * 72 + r] = (unsigned short)(vr0.x & 0xffff);
        vh[(d0 + 1) * 72 + r] = (unsigned short)(vr0.x >> 16);
        vh[(d0 + 2) * 72 + r] = (unsigned short)(vr0.y & 0xffff);
        vh[(d0 + 3) * 72 + r] = (unsigned short)(vr0.y >> 16);
        vh[(d0 + 4) * 72 + r] = (unsigned short)(vr0.z & 0xffff);
        vh[(d0 + 5) * 72 + r] = (unsigned short)(vr0.z >> 16);
        vh[(d0 + 6) * 72 + r] = (unsigned short)(vr0.w & 0xffff);
        vh[(d0 + 7) * 72 + r] = (unsigned short)(vr0.w >> 16);
        vh[(d0 + 8) * 72 + r]  = (unsigned short)(vr1.x & 0xffff);
        vh[(d0 + 9) * 72 + r]  = (unsigned short)(vr1.x >> 16);
        vh[(d0 + 10) * 72 + r] = (unsigned short)(vr1.y & 0xffff);
        vh[(d0 + 11) * 72 + r] = (unsigned short)(vr1.y >> 16);
        vh[(d0 + 12) * 72 + r] = (unsigned short)(vr1.z & 0xffff);
        vh[(d0 + 13) * 72 + r] = (unsigned short)(vr1.z >> 16);
        vh[(d0 + 14) * 72 + r] = (unsigned short)(vr1.w & 0xffff);
        vh[(d0 + 15) * 72 + r] = (unsigned short)(vr1.w >> 16);
    }
    __syncthreads();

    unsigned qa[4][4];
    int q0 = w * 16 + tr;
    #pragma unroll
    for (int s2 = 0; s2 < 4; s2++) {
        qa[s2][0] = Qs[q0 * 36 + 8 * s2 + tc];
        qa[s2][1] = Qs[(q0 + 8) * 36 + 8 * s2 + tc];
        qa[s2][2] = Qs[q0 * 36 + 8 * s2 + tc + 4];
        qa[s2][3] = Qs[(q0 + 8) * 36 + 8 * s2 + tc + 4];
    }

    float oacc[8][4];
    #pragma unroll
    for (int ni = 0; ni < 8; ni++)
        #pragma unroll
        for (int c = 0; c < 4; c++) oacc[ni][c] = 0.f;
    float m0v = -1e30f, m1v = -1e30f, l0 = 0.f, l1 = 0.f;

    int sb = 0;
    for (int t = 0; t < nt; t++) {
        asm volatile("cp.async.wait_group 0;");
        __syncthreads();

        if (t + 1 < nt) {
            const unsigned short* ks = kSrcBase + (size_t)(t + 1) * 64 * 1536;
            CP16(kDst[sb ^ 1],      ks);
            CP16(kDst[sb ^ 1] + 16, ks + 8);
            asm volatile("cp.async.commit_group;");
            const uint4* vp = (const uint4*)(vSrcBase + (size_t)(t + 1) * 64 * 1536);
            vr0 = vp[0]; vr1 = vp[1];
        }

        const unsigned* Kb = sb ? Ks1 : Ks0;
        const unsigned* Vb = sb ? Vs1 : Vs0;

        float sacc[8][4];
        #pragma unroll
        for (int ni = 0; ni < 8; ni++) {
            #pragma unroll
            for (int c = 0; c < 4; c++) sacc[ni][c] = 0.f;
            int nb = (ni * 8 + tr) * 36;
            #pragma unroll
            for (int s2 = 0; s2 < 4; s2++) {
                unsigned b0 = Kb[nb + 8 * s2 + tc];
                unsigned b1 = Kb[nb + 8 * s2 + tc + 4];
                MMA_BF16(sacc[ni], qa[s2][0], qa[s2][1], qa[s2][2], qa[s2][3], b0, b1);
            }
        }

        #pragma unroll
        for (int ni = 0; ni < 8; ni++) {
            int col = t * 64 + ni * 8 + 2 * tc;
            float bb0 = (col < len)     ? 0.f : -1e9f;
            float bb1 = (col + 1 < len) ? 0.f : -1e9f;
            sacc[ni][0] = sacc[ni][0] * 0.125f + bb0;
            sacc[ni][1] = sacc[ni][1] * 0.125f + bb1;
            sacc[ni][2] = sacc[ni][2] * 0.125f + bb0;
            sacc[ni][3] = sacc[ni][3] * 0.125f + bb1;
        }

        float t0 = -1e30f, t1 = -1e30f;
        #pragma unroll
        for (int ni = 0; ni < 8; ni++) {
            t0 = fmaxf(t0, fmaxf(sacc[ni][0], sacc[ni][1]));
            t1 = fmaxf(t1, fmaxf(sacc[ni][2], sacc[ni][3]));
        }
        t0 = fmaxf(t0, __shfl_xor_sync(0xffffffffu, t0, 1));
        t0 = fmaxf(t0, __shfl_xor_sync(0xffffffffu, t0, 2));
        t1 = fmaxf(t1, __shfl_xor_sync(0xffffffffu, t1, 1));
        t1 = fmaxf(t1, __shfl_xor_sync(0xffffffffu, t1, 2));
        float mn0 = fmaxf(m0v, t0), mn1 = fmaxf(m1v, t1);
        float c0 = __expf(m0v - mn0), c1 = __expf(m1v - mn1);
        l0 *= c0; l1 *= c1;
        #pragma unroll
        for (int ni = 0; ni < 8; ni++) {
            oacc[ni][0] *= c0; oacc[ni][1] *= c0;
            oacc[ni][2] *= c1; oacc[ni][3] *= c1;
        }
        float s0 = 0.f, s1 = 0.f;
        #pragma unroll
        for (int ni = 0; ni < 8; ni++) {
            float p0 = __expf(sacc[ni][0] - mn0);
            float p1 = __expf(sacc[ni][1] - mn0);
            float p2 = __expf(sacc[ni][2] - mn1);
            float p3 = __expf(sacc[ni][3] - mn1);
            sacc[ni][0] = p0; sacc[ni][1] = p1;
            sacc[ni][2] = p2; sacc[ni][3] = p3;
            s0 += p0 + p1; s1 += p2 + p3;
        }
        s0 += __shfl_xor_sync(0xffffffffu, s0, 1);
        s0 += __shfl_xor_sync(0xffffffffu, s0, 2);
        s1 += __shfl_xor_sync(0xffffffffu, s1, 1);
        s1 += __shfl_xor_sync(0xffffffffu, s1, 2);
        l0 += s0; l1 += s1;
        m0v = mn0; m1v = mn1;

        unsigned pa[4][4];
        #pragma unroll
        for (int s2 = 0; s2 < 4; s2++) {
            pa[s2][0] = packbf(sacc[2 * s2][0],     sacc[2 * s2][1]);
            pa[s2][1] = packbf(sacc[2 * s2][2],     sacc[2 * s2][3]);
            pa[s2][2] = packbf(sacc[2 * s2 + 1][0], sacc[2 * s2 + 1][1]);
            pa[s2][3] = packbf(sacc[2 * s2 + 1][2], sacc[2 * s2 + 1][3]);
        }

        #pragma unroll
        for (int ni = 0; ni < 8; ni++) {
            int nb = (ni * 8 + tr) * 36;
            #pragma unroll
            for (int s2 = 0; s2 < 4; s2++) {
                unsigned b0 = Vb[nb + 8 * s2 + tc];
                unsigned b1 = Vb[nb + 8 * s2 + tc + 4];
                MMA_BF16(oacc[ni], pa[s2][0], pa[s2][1], pa[s2][2], pa[s2][3], b0, b1);
            }
        }

        if (t + 1 < nt) {
            unsigned short* vh = (unsigned short*)(sb ? Vs0 : Vs1);
            int d0 = qq * 16;
            vh[(d0 + 0) * 72 + r] = (unsigned short)(vr0.x & 0xffff);
            vh[(d0 + 1) * 72 + r] = (unsigned short)(vr0.x >> 16);
            vh[(d0 + 2) * 72 + r] = (unsigned short)(vr0.y & 0xffff);
            vh[(d0 + 3) * 72 + r] = (unsigned short)(vr0.y >> 16);
            vh[(d0 + 4) * 72 + r] = (unsigned short)(vr0.z & 0xffff);
            vh[(d0 + 5) * 72 + r] = (unsigned short)(vr0.z >> 16);
            vh[(d0 + 6) * 72 + r] = (unsigned short)(vr0.w & 0xffff);
            vh[(d0 + 7) * 72 + r] = (unsigned short)(vr0.w >> 16);
            vh[(d0 + 8) * 72 + r]  = (unsigned short)(vr1.x & 0xffff);
            vh[(d0 + 9) * 72 + r]  = (unsigned short)(vr1.x >> 16);
            vh[(d0 + 10) * 72 + r] = (unsigned short)(vr1.y & 0xffff);
            vh[(d0 + 11) * 72 + r] = (unsigned short)(vr1.y >> 16);
            vh[(d0 + 12) * 72 + r] = (unsigned short)(vr1.z & 0xffff);
            vh[(d0 + 13) * 72 + r] = (unsigned short)(vr1.z >> 16);
            vh[(d0 + 14) * 72 + r] = (unsigned short)(vr1.w & 0xffff);
            vh[(d0 + 15) * 72 + r] = (unsigned short)(vr1.w >> 16);
        }
        sb ^= 1;
    }

    float i0 = 1.0f / l0, i1 = 1.0f / l1;
    int orow0 = b * 1024 + qt * 128 + w * 16 + tr;
    #pragma unroll
    for (int ni = 0; ni < 8; ni++) {
        int col = h * 64 + ni * 8 + 2 * tc;
        out[orow0 * 256 + col / 2]       = packbf(oacc[ni][0] * i0, oacc[ni][1] * i0);
        out[(orow0 + 8) * 256 + col / 2] = packbf(oacc[ni][2] * i1, oacc[ni][3] * i1);
    }
}

// ---------------- codebook argmax: compact z rows, 16-way V split ----------------
__global__ void argmax_kernel(const float* __restrict__ z, const float* __restrict__ emb) {
    int rt = blockIdx.y;
    int M = g_M;
    if (rt * 16 >= M) return;
    __shared__ float zs[16][512];
    int tid = threadIdx.x;
    for (int it = 0; it < 32; it++) {
        int idx = it * 256 + tid;
        int r = idx >> 9, c = idx & 511;
        zs[r][c] = z[(size_t)(rt * 16 + r) * 512 + c];
    }
    __syncthreads();

    float bestv[16]; int besti[16];
    #pragma unroll
    for (int r2 = 0; r2 < 16; r2++) { bestv[r2] = -1e30f; besti[r2] = 0; }

    int vbase = blockIdx.x * 512;
    for (int it = 0; it < 2; it++) {
        int v = vbase + it * 256 + tid;
        float acc[16];
        #pragma unroll
        for (int r2 = 0; r2 < 16; r2++) acc[r2] = 0.f;
        for (int e = 0; e < 512; e += 4) {
            float ev0 = emb[(size_t)(e + 0) * VV + v];
            float ev1 = emb[(size_t)(e + 1) * VV + v];
            float ev2 = emb[(size_t)(e + 2) * VV + v];
            float ev3 = emb[(size_t)(e + 3) * VV + v];
            #pragma unroll
            for (int r2 = 0; r2 < 16; r2++) {
                float4 zq = *(const float4*)&zs[r2][e];
                acc[r2] += zq.x * ev0 + zq.y * ev1 + zq.z * ev2 + zq.w * ev3;
            }
        }
        float pen = g_e2[v];
        #pragma unroll
        for (int r2 = 0; r2 < 16; r2++) {
            float sc = acc[r2] - pen;
            if (sc > bestv[r2]) { bestv[r2] = sc; besti[r2] = v; }
        }
    }
    __syncthreads();

    __shared__ float sval[256];
    __shared__ int sidx[256];
    for (int r2 = 0; r2 < 16; r2++) {
        int mrow = rt * 16 + r2;
        sval[tid] = bestv[r2];
        sidx[tid] = besti[r2];
        __syncthreads();
        for (int off = 128; off; off >>= 1) {
            if (tid < off) {
                float v2 = sval[tid + off]; int i2 = sidx[tid + off];
                if (v2 > sval[tid] || (v2 == sval[tid] && i2 < sidx[tid])) {
                    sval[tid] = v2; sidx[tid] = i2;
                }
            }
            __syncthreads();
        }
        if (tid == 0 && mrow < M) {
            g_pbv[mrow * 16 + blockIdx.x] = sval[0];
            g_pbi[mrow * 16 + blockIdx.x] = sidx[0];
        }
        __syncthreads();
    }
}

__global__ void combine_kernel() {
    int m = blockIdx.x * 256 + threadIdx.x;
    if (m >= g_M) return;
    float bv = -1e30f; int bi = 0x7fffffff;
    #pragma unroll
    for (int qd = 0; qd < 16; qd++) {
        float v = g_pbv[m * 16 + qd]; int i = g_pbi[m * 16 + qd];
        if (v > bv || (v == bv && i < bi)) { bv = v; bi = i; }
    }
    g_tgt[m] = bi;
}

// ---------------- cross entropy over materialized masked logits ----------------
__global__ void ce2_kernel(const float* __restrict__ logits) {
    int m = blockIdx.x;
    if (m >= g_M) return;
    const float4* row4 = (const float4*)(logits + (size_t)m * VV);
    int tid = threadIdx.x;   // 256
    __shared__ float sm[256];
    float mx = -1e30f;
    for (int i = tid; i < VV / 4; i += 256) {
        float4 v = row4[i];
        mx = fmaxf(mx, fmaxf(fmaxf(v.x, v.y), fmaxf(v.z, v.w)));
    }
    sm[tid] = mx;
    __syncthreads();
    for (int off = 128; off; off >>= 1) {
        if (tid < off) sm[tid] = fmaxf(sm[tid], sm[tid + off]);
        __syncthreads();
    }
    float mmax = sm[0];
    __syncthreads();
    float se = 0.f;
    for (int i = tid; i < VV / 4; i += 256) {
        float4 v = row4[i];
        se += __expf(v.x - mmax) + __expf(v.y - mmax)
            + __expf(v.z - mmax) + __expf(v.w - mmax);
    }
    sm[tid] = se;
    __syncthreads();
    for (int off = 128; off; off >>= 1) {
        if (tid < off) sm[tid] += sm[tid + off];
        __syncthreads();
    }
    if (tid == 0) {
        float lse = mmax + __logf(sm[0]);
        g_ent[m] = lse - ((const float*)row4)[g_tgt[m]];
    }
}

__global__ void loss_kernel(float* __restrict__ out) {
    int M = g_M;
    int tid = threadIdx.x;
    float acc = 0.f;
    for (int i = tid; i < M; i += 1024) acc += g_ent[i];
    __shared__ float s[1024];
    s[tid] = acc;
    __syncthreads();
    for (int off = 512; off; off >>= 1) {
        if (tid < off) s[tid] += s[tid + off];
        __syncthreads();
    }
    if (tid == 0) out[0] = s[0] / (float)M;
}

// ---------------- host driver (single stream) ----------------
extern "C" void kernel_launch(void* const* d_in, const int* in_sizes, int n_in,
                              void* d_out, int out_size) {
    const float* xs      = (const float*)d_in[0];
    const int*   lens    = (const int*)d_in[1];
    const void*  mask    = d_in[2];
    const float* W_embed = (const float*)d_in[3];
    const float* ln1_s   = (const float*)d_in[4];
    const float* ln1_b   = (const float*)d_in[5];
    const float* Wqkv    = (const float*)d_in[6];
    const float* Wo      = (const float*)d_in[7];
    const float* ln2_s   = (const float*)d_in[8];
    const float* ln2_b   = (const float*)d_in[9];
    const float* W1      = (const float*)d_in[10];
    const float* W2      = (const float*)d_in[11];
    const float* an_s    = (const float*)d_in[12];
    const float* an_b    = (const float*)d_in[13];
    const float* iln_s   = (const float*)d_in[14];
    const float* iln_b   = (const float*)d_in[15];
    const float* memb    = (const float*)d_in[16];
    const float* top     = (const float*)d_in[17];
    const float* proj    = (const float*)d_in[18];
    const float* emb     = (const float*)d_in[19];
    float* out = (float*)d_out;

    cudaFuncSetAttribute(bfgemm, cudaFuncAttributeMaxDynamicSharedMemorySize, BF_SMEM);
    cudaFuncSetAttribute(attn_mma_kernel, cudaFuncAttributeMaxDynamicSharedMemorySize, ATT_SMEM);

    void *bhx, *bh, *bxe, *bz, *blog;
    void *bxsbf, *bhbf, *bqkvbf, *bobf, *bfbf, *bgz;
    void *bwe, *bwqkv, *bwo, *bw1, *bw2, *btop, *bridx;
    cudaGetSymbolAddress(&bhx,  g_hx);
    cudaGetSymbolAddress(&bh,   g_h);
    cudaGetSymbolAddress(&bxe,  g_xe);
    cudaGetSymbolAddress(&bz,   g_z);
    cudaGetSymbolAddress(&blog, g_logits);
    cudaGetSymbolAddress(&bxsbf,  g_xs_bf);
    cudaGetSymbolAddress(&bhbf,   g_h_bf);
    cudaGetSymbolAddress(&bqkvbf, g_qkv_bf);
    cudaGetSymbolAddress(&bobf,   g_o_bf);
    cudaGetSymbolAddress(&bfbf,   g_f_bf);
    cudaGetSymbolAddress(&bgz,    g_gz_bf);
    cudaGetSymbolAddress(&bwe,   g_we_bf);
    cudaGetSymbolAddress(&bwqkv, g_wqkv_bf);
    cudaGetSymbolAddress(&bwo,   g_wo_bf);
    cudaGetSymbolAddress(&bw1,   g_w1_bf);
    cudaGetSymbolAddress(&bw2,   g_w2_bf);
    cudaGetSymbolAddress(&bridx, g_rowidx);

    cudaGetSymbolAddress(&btop,  g_top_bf);

    int ne = DD * DD / 2;
    int nx = NROWS * DD / 2;
    int n1 = LL * DD * 3 * DD / 2;
    int n2 = LL * DD * DD / 2;
    int n3 = LL * DD * FF / 2;
    int n4 = DD * VV / 2;

    detect_mask_kernel<<<1, 256>>>(mask);
    compact_kernel<<<1, 1024>>>(mask, lens);
    convert_kernel<<<(nx + 255) / 256, 256>>>((const float2*)xs,      (unsigned*)bxsbf, nx);
    convert_kernel<<<(ne + 255) / 256, 256>>>((const float2*)W_embed, (unsigned*)bwe,   ne);
    convert_kernel<<<(n1 + 255) / 256, 256>>>((const float2*)Wqkv,    (unsigned*)bwqkv, n1);

    // encoder input: bf16 embed + fused PE + mask substitution (-> bxe fp32)
    bfgemm<<<dim3(4, 64), 256, BF_SMEM>>>((const unsigned short*)bxsbf,
                                  (const unsigned short*)bwe,
                                  bxe, nullptr, NROWS, DD, DD, 4, 2, lens, mask, memb);
    ln_bf_kernel<<<NROWS, 128>>>((const float*)bxe, (unsigned*)bhbf, ln1_s, ln1_b, lens);
    bfgemm<<<dim3(12, 64), 256, BF_SMEM>>>((const unsigned short*)bhbf,
                                  (const unsigned short*)bwqkv,
                                  bqkvbf, nullptr, NROWS, 3 * DD, DD, 3, 2, lens, nullptr, nullptr);

    // remaining weight conversions + target-path prep (independent of encoder)
    convert_kernel<<<(n2 + 255) / 256, 256>>>((const float2*)Wo,  (unsigned*)bwo,  n2);
    convert_kernel<<<(n3 + 255) / 256, 256>>>((const float2*)W1,  (unsigned*)bw1,  n3);
    convert_kernel<<<(n3 + 255) / 256, 256>>>((const float2*)W2,  (unsigned*)bw2,  n3);
    convert_kernel<<<(n4 + 255) / 256, 256>>>((const float2*)top, (unsigned*)btop, n4);
    e2_kernel<<<VV / 256, 256>>>(emb);

    // target path: exact embed at masked rows only (gathered A, exact PE), then LN/proj/argmax
    sgemm<<<dim3(4, MPAD / 128), 256>>>(xs, W_embed, (float*)bhx, nullptr,
                                        MPAD, DD, DD, 3, (const int*)bridx);
    ln_plain_f32<<<MPAD, 128>>>((const float*)bhx, (float*)bh, iln_s, iln_b);
    sgemm<<<dim3(4, MPAD / 128), 256>>>((const float*)bh, proj, (float*)bz, nullptr,
                                        MPAD, DD, DD, 0, nullptr);
    argmax_kernel<<<dim3(16, MPAD / 16), 256>>>((const float*)bz, emb);
    combine_kernel<<<MPAD / 256, 256>>>();

    // encoder layer 0 (QKV already done)
    attn_mma_kernel<<<dim3(8, 64), 256, ATT_SMEM>>>((const unsigned short*)bqkvbf, lens, (unsigned*)bobf);
    bfgemm<<<dim3(4, 64), 256, BF_SMEM>>>((const unsigned short*)bobf,
                                 (const unsigned short*)bwo,
                                 bxe, (const float*)bxe, NROWS, DD, DD, 1, 2, lens, nullptr, nullptr);
    ln_bf_kernel<<<NROWS, 128>>>((const float*)bxe, (unsigned*)bhbf, ln2_s, ln2_b, lens);
    bfgemm<<<dim3(16, 64), 256, BF_SMEM>>>((const unsigned short*)bhbf,
                                  (const unsigned short*)bw1,
                                  bfbf, nullptr, NROWS, FF, DD, 2, 2, lens, nullptr, nullptr);
    bfgemm<<<dim3(4, 64), 256, BF_SMEM>>>((const unsigned short*)bfbf,
                                 (const unsigned short*)bw2,
                                 bxe, (const float*)bxe, NROWS, DD, FF, 1, 2, lens, nullptr, nullptr);

    // encoder layers 1..5
    for (int l = 1; l < LL; l++) {
        ln_bf_kernel<<<NROWS, 128>>>((const float*)bxe, (unsigned*)bhbf,
                                     ln1_s + l * DD, ln1_b + l * DD, lens);
        bfgemm<<<dim3(12, 64), 256, BF_SMEM>>>((const unsigned short*)bhbf,
                                      (const unsigned short*)bwqkv + (size_t)l * DD * 3 * DD,
                                      bqkvbf, nullptr, NROWS, 3 * DD, DD, 3, 2, lens, nullptr, nullptr);
        attn_mma_kernel<<<dim3(8, 64), 256, ATT_SMEM>>>((const unsigned short*)bqkvbf, lens, (unsigned*)bobf);
        bfgemm<<<dim3(4, 64), 256, BF_SMEM>>>((const unsigned short*)bobf,
                                     (const unsigned short*)bwo + (size_t)l * DD * DD,
                                     bxe, (const float*)bxe, NROWS, DD, DD, 1, 2, lens, nullptr, nullptr);
        ln_bf_kernel<<<NROWS, 128>>>((const float*)bxe, (unsigned*)bhbf,
                                     ln2_s + l * DD, ln2_b + l * DD, lens);
        bfgemm<<<dim3(16, 64), 256, BF_SMEM>>>((const unsigned short*)bhbf,
                                      (const unsigned short*)bw1 + (size_t)l * DD * FF,
                                      bfbf, nullptr, NROWS, FF, DD, 2, 2, lens, nullptr, nullptr);
        bfgemm<<<dim3(4, 64), 256, BF_SMEM>>>((const unsigned short*)bfbf,
                                     (const unsigned short*)bw2 + (size_t)l * FF * DD,
                                     bxe, (const float*)bxe, NROWS, DD, FF, 1, 2, lens, nullptr, nullptr);
    }

    // gathered final LN (masked rows only) -> bf16 logits GEMM -> CE -> loss
    gather_ln_bf<<<MPAD, 128>>>((const float*)bxe, (unsigned*)bgz, an_s, an_b);
    bfgemm<<<dim3(64, MPAD / 128), 256, BF_SMEM>>>((const unsigned short*)bgz,
                                  (const unsigned short*)btop,
                                  blog, nullptr, MPAD, VV, DD, 0, 1, nullptr, nullptr, nullptr);
    ce2_kernel<<<MPAD, 256>>>((const float*)blog);
    loss_kernel<<<1, 1024>>>(out);
}